// round 11
// baseline (speedup 1.0000x reference)
#include <cuda_runtime.h>
#include <cuda_fp16.h>
#include <cstdint>

// x[32768,2048] fp32, bank[20,2048] fp32 -> out[32768,2048] fp32
constexpr int FEA    = 2048;
constexpr int NBANK  = 20;
constexpr int TILE_M = 32;             // 1024 tiles
constexpr int CHUNK  = 256;            // x cols per chunk
constexpr int NCH    = FEA / CHUNK;    // 8
constexpr int DEPTH  = 4;              // fp16 slot ring
constexpr int NTH    = 320;            // 8 consumer warps + 2 producer warps
constexpr float LAMBDA = 0.0025f;

// SMEM map (220224 B, 1 CTA/SM)
constexpr int SM_BANK  = 0;                         // [20 j][2048 k] fp16 swz
constexpr int BANKB    = NBANK * 4096;              // 81920
constexpr int SM_ZP    = BANKB;                     // 1KB zero page
constexpr int SM_STAGE = SM_ZP + 1024;              // 82944: fp32 stage 2x32KB
constexpr int STAGEB   = TILE_M * CHUNK * 4;        // 32768
constexpr int SM_X     = SM_STAGE + 2 * STAGEB;     // 148480: fp16 ring 4x16KB
constexpr int XSLOTB   = TILE_M * CHUNK * 2;        // 16384
constexpr int SM_LOGIT = SM_X + DEPTH * XSLOTB;     // 214016: [32][32] f32
constexpr int SM_ATT   = SM_LOGIT + 32 * 32 * 4;    // 218112: [32][32] fp16
constexpr int SM_MB    = SM_ATT + 32 * 32 * 2;      // 220160: 4 x (full,empty)
constexpr int SM_TOTAL = SM_MB + 64;                // 220224

__device__ __forceinline__ uint32_t s2u(const void* p) {
    uint32_t a;
    asm("{ .reg .u64 t; cvta.to.shared.u64 t, %1; cvt.u32.u64 %0, t; }"
        : "=r"(a) : "l"(p));
    return a;
}
__device__ __forceinline__ void ldsm4(uint32_t a, uint32_t& r0, uint32_t& r1,
                                      uint32_t& r2, uint32_t& r3) {
    asm volatile("ldmatrix.sync.aligned.m8n8.x4.shared.b16 {%0,%1,%2,%3}, [%4];"
                 : "=r"(r0), "=r"(r1), "=r"(r2), "=r"(r3) : "r"(a));
}
__device__ __forceinline__ void ldsm2(uint32_t a, uint32_t& r0, uint32_t& r1) {
    asm volatile("ldmatrix.sync.aligned.m8n8.x2.shared.b16 {%0,%1}, [%2];"
                 : "=r"(r0), "=r"(r1) : "r"(a));
}
__device__ __forceinline__ void ldsm4t(uint32_t a, uint32_t& r0, uint32_t& r1,
                                       uint32_t& r2, uint32_t& r3) {
    asm volatile("ldmatrix.sync.aligned.m8n8.x4.trans.shared.b16 {%0,%1,%2,%3}, [%4];"
                 : "=r"(r0), "=r"(r1), "=r"(r2), "=r"(r3) : "r"(a));
}
__device__ __forceinline__ void mma16816(float& d0, float& d1, float& d2, float& d3,
                                         uint32_t a0, uint32_t a1, uint32_t a2, uint32_t a3,
                                         uint32_t b0, uint32_t b1) {
    asm volatile(
        "mma.sync.aligned.m16n8k16.row.col.f32.f16.f16.f32 "
        "{%0,%1,%2,%3}, {%4,%5,%6,%7}, {%8,%9}, {%0,%1,%2,%3};"
        : "+f"(d0), "+f"(d1), "+f"(d2), "+f"(d3)
        : "r"(a0), "r"(a1), "r"(a2), "r"(a3), "r"(b0), "r"(b1));
}
__device__ __forceinline__ float tanh_fast(float v) {
    float r;
    asm("tanh.approx.f32 %0, %1;" : "=f"(r) : "f"(v));
    return r;
}
__device__ __forceinline__ uint32_t h2bits(__half2 h) {
    return *reinterpret_cast<uint32_t*>(&h);
}
__device__ __forceinline__ void cp16(uint32_t dst, const float* src) {
    asm volatile("cp.async.cg.shared.global [%0], [%1], 16;" :: "r"(dst), "l"(src));
}
__device__ __forceinline__ void mbar_init(uint32_t a, uint32_t cnt) {
    asm volatile("mbarrier.init.shared.b64 [%0], %1;" :: "r"(a), "r"(cnt) : "memory");
}
__device__ __forceinline__ void mbar_arrive(uint32_t a) {
    asm volatile("mbarrier.arrive.shared.b64 _, [%0];" :: "r"(a) : "memory");
}
__device__ __forceinline__ void mbar_wait(uint32_t a, uint32_t parity) {
    asm volatile(
        "{\n\t.reg .pred P1;\n\t"
        "WL%=:\n\t"
        "mbarrier.try_wait.parity.shared.b64 P1, [%0], %1;\n\t"
        "@P1 bra WD%=;\n\t"
        "bra WL%=;\n\t"
        "WD%=:\n\t}"
        :: "r"(a), "r"(parity) : "memory");
}

extern __shared__ char smc[];

__global__ void __launch_bounds__(NTH, 1)
memunit_ws(const float* __restrict__ x,
           const float* __restrict__ bank,
           float* __restrict__ out,
           int n_tiles)
{
    const uint32_t sbase = s2u(smc);
    const int tid  = threadIdx.x;
    const int warp = tid >> 5;
    const int lane = tid & 31;
    const int G    = gridDim.x;
    const int bid  = (int)blockIdx.x;
    const int my_tiles = (n_tiles - bid + G - 1) / G;

    // ---- init: bank fp16 [20 j][2048 k] swz, zero page, mbarriers ---------
    for (int idx = tid; idx < NBANK * FEA; idx += NTH) {
        const int j = idx >> 11, k = idx & (FEA - 1);
        *reinterpret_cast<__half*>(smc + SM_BANK + j * 4096 + ((2 * k) ^ ((j & 7) << 4)))
            = __float2half(bank[idx]);
    }
    for (int i = tid; i < 1024 / 4; i += NTH)
        reinterpret_cast<uint32_t*>(smc + SM_ZP)[i] = 0u;
    if (tid == 0) {
        #pragma unroll
        for (int s = 0; s < DEPTH; s++) {
            mbar_init(sbase + SM_MB + s * 16,     64);   // full: 64 producer thr
            mbar_init(sbase + SM_MB + s * 16 + 8, 256);  // empty: 256 consumer thr
        }
    }
    __syncthreads();   // last CTA-wide barrier

    if (warp >= 8) {
        // ==================== PRODUCER (2 warps, 64 threads) ================
        const int pt = tid - 256;                 // 0..63
        const int total = my_tiles * NCH;
        int st = 0, pph = 1;                      // producer phase starts 1

        auto cp_issue = [&](int g) {
            const int tile = bid + (g >> 3) * G;
            const int c    = g & 7;
            const uint32_t dst = sbase + SM_STAGE + (g & 1) * STAGEB;
            const float* src = x + (long)tile * TILE_M * FEA + c * CHUNK;
            #pragma unroll
            for (int i = 0; i < 32; i++) {
                const int e = i * 64 + pt;        // float4 index 0..2047
                cp16(dst + e * 16, src + (e >> 6) * FEA + (e & 63) * 4);
            }
            asm volatile("cp.async.commit_group;" ::: "memory");
        };

        if (total > 0) cp_issue(0);
        for (int g = 0; g < total; g++) {
            if (g + 1 < total) {
                cp_issue(g + 1);
                asm volatile("cp.async.wait_group 1;" ::: "memory");
            } else {
                asm volatile("cp.async.wait_group 0;" ::: "memory");
            }
            mbar_wait(sbase + SM_MB + st * 16 + 8, pph);   // empty[st]

            const char* sp = smc + SM_STAGE + (g & 1) * STAGEB;
            char*       dp = smc + SM_X + st * XSLOTB;
            #pragma unroll
            for (int i = 0; i < 32; i++) {
                const int e = i * 64 + pt;
                const int row = e >> 6, col4 = e & 63;
                const float4 v = *reinterpret_cast<const float4*>(sp + e * 16);
                uint2 pkt;
                pkt.x = h2bits(__floats2half2_rn(v.x, v.y));
                pkt.y = h2bits(__floats2half2_rn(v.z, v.w));
                *reinterpret_cast<uint2*>(dp + row * 512 + ((col4 * 8) ^ ((row & 7) << 4)))
                    = pkt;
            }
            mbar_arrive(sbase + SM_MB + st * 16);          // full[st]
            if (++st == DEPTH) { st = 0; pph ^= 1; }
        }
        return;
    }

    // ======================= CONSUMER (8 warps) =============================
    const int mh = warp >> 2;              // m-half: rows mh*16..+15
    const int nt = warp & 3;               // n-tile / n-quarter

    const int arow = mh * 16 + (lane & 7) + ((lane & 8) ? 8 : 0);
    const int akb  = (lane & 16) ? 16 : 0;
    const int asw  = (arow & 7) << 4;
    // GEMM1 B (non-trans x2): rows j = nt*8 + (lane&7), clamp j >= 20
    const int brow = nt * 8 + (lane & 7);
    const int bkb  = (lane & 8) ? 16 : 0;
    const int bsw  = (brow & 7) << 4;
    const bool bvalid = brow < NBANK;
    const uint32_t bb  = sbase + SM_BANK + brow * 4096;
    const uint32_t zpA = sbase + SM_ZP + (lane & 7) * 16;
    // GEMM2 B (trans x4): j = lane, clamp lane >= 20
    const bool tvalid = lane < NBANK;
    const uint32_t btl = sbase + SM_BANK + (tvalid ? lane : 0) * 4096;
    const uint32_t zpB = sbase + SM_ZP + lane * 16;
    const int swj = (lane & 7) << 4;
    // D / logit / out rows
    const int lr  = mh * 16 + (lane >> 2);
    const int lc2 = (lane & 3) * 2;

    int st = 0, cph = 0;                   // consumer phase starts 0
    uint32_t aA0[4], aA1[4];               // att frags for previous tile

    for (int it = 0; it <= my_tiles; it++) {
        const bool hasG1 = it < my_tiles;
        const bool hasG2 = it > 0;
        const long row0w = (long)(bid + (it - 1) * G) * TILE_M;

        float d0 = 0.f, d1 = 0.f, d2 = 0.f, d3 = 0.f;
        float* orow0 = out + (row0w + lr) * FEA + lc2;
        float* orow1 = out + (row0w + lr + 8) * FEA + lc2;

        #pragma unroll 1
        for (int c = 0; c < NCH; c++) {
            if (hasG1) {
                mbar_wait(sbase + SM_MB + st * 16, cph);   // full[st]
                const uint32_t xs = sbase + SM_X + st * XSLOTB + arow * 512;
                #pragma unroll
                for (int ks = 0; ks < 16; ks++) {
                    uint32_t a0, a1, a2, a3, b0, b1;
                    ldsm4(xs + ((ks * 32 + akb) ^ asw), a0, a1, a2, a3);
                    ldsm2(bvalid ? bb + ((c * 512 + ks * 32 + bkb) ^ bsw) : zpA, b0, b1);
                    mma16816(d0, d1, d2, d3, a0, a1, a2, a3, b0, b1);
                }
                mbar_arrive(sbase + SM_MB + st * 16 + 8);  // empty[st]
                if (++st == DEPTH) { st = 0; cph ^= 1; }
            }

            if (hasG2) {
                #pragma unroll
                for (int i = 0; i < 8; i++) {
                    const int nb = (c * 32 + nt * 8 + i) * 8;
                    uint32_t b00, b01, b10, b11;
                    ldsm4t(tvalid ? btl + ((nb * 2) ^ swj) : zpB, b00, b01, b10, b11);
                    float e0 = 0.f, e1 = 0.f, e2 = 0.f, e3 = 0.f;
                    mma16816(e0, e1, e2, e3, aA0[0], aA0[1], aA0[2], aA0[3], b00, b01);
                    mma16816(e0, e1, e2, e3, aA1[0], aA1[1], aA1[2], aA1[3], b10, b11);
                    *reinterpret_cast<float2*>(orow0 + nb) =
                        make_float2(tanh_fast(e0), tanh_fast(e1));
                    *reinterpret_cast<float2*>(orow1 + nb) =
                        make_float2(tanh_fast(e2), tanh_fast(e3));
                }
            }
        }

        if (hasG1) {
            // ---- logits -> SMEM (consumer-only barrier) ------------------
            float* lg = reinterpret_cast<float*>(smc + SM_LOGIT);
            *reinterpret_cast<float2*>(&lg[lr * 32 + nt * 8 + lc2])       = make_float2(d0, d1);
            *reinterpret_cast<float2*>(&lg[(lr + 8) * 32 + nt * 8 + lc2]) = make_float2(d2, d3);
            asm volatile("bar.sync 1, 256;" ::: "memory");

            if (tid < 32) {
                float att[NBANK];
                #pragma unroll
                for (int j = 0; j < NBANK; j++) att[j] = lg[tid * 32 + j];

                float m = att[0];
                #pragma unroll
                for (int j = 1; j < NBANK; j++) m = fmaxf(m, att[j]);
                float s = 0.f;
                #pragma unroll
                for (int j = 0; j < NBANK; j++) { float e = __expf(att[j] - m); att[j] = e; s += e; }
                const float inv = 1.0f / s;

                float m2 = 0.f;   // att >= 0 => softshrink = max(att - lambda, 0)
                #pragma unroll
                for (int j = 0; j < NBANK; j++) {
                    float a = fmaxf(att[j] * inv - LAMBDA, 0.f);
                    att[j] = a;
                    m2 = fmaxf(m2, a);
                }
                float s2 = 0.f;
                #pragma unroll
                for (int j = 0; j < NBANK; j++) { float e = __expf(att[j] - m2); att[j] = e; s2 += e; }
                const float inv2 = 1.0f / s2;

                __half2* av = reinterpret_cast<__half2*>(smc + SM_ATT + tid * 64);
                #pragma unroll
                for (int jp = 0; jp < 10; jp++)
                    av[jp] = __floats2half2_rn(att[2 * jp] * inv2, att[2 * jp + 1] * inv2);
                #pragma unroll
                for (int jp = 10; jp < 16; jp++)
                    av[jp] = __floats2half2_rn(0.f, 0.f);
            }
            asm volatile("bar.sync 1, 256;" ::: "memory");

            const uint32_t ab = sbase + SM_ATT + arow * 64 + ((lane & 16) ? 16 : 0);
            ldsm4(ab,      aA0[0], aA0[1], aA0[2], aA0[3]);   // k = j 0..15
            ldsm4(ab + 32, aA1[0], aA1[1], aA1[2], aA1[3]);   // k = j 16..31
        }
    }
}

extern "C" void kernel_launch(void* const* d_in, const int* in_sizes, int n_in,
                              void* d_out, int out_size)
{
    const float* x    = reinterpret_cast<const float*>(d_in[0]);
    const float* bank = reinterpret_cast<const float*>(d_in[1]);
    float* out        = reinterpret_cast<float*>(d_out);

    const int rows    = in_sizes[0] / FEA;   // 32768
    const int n_tiles = rows / TILE_M;       // 1024

    cudaFuncSetAttribute(memunit_ws,
                         cudaFuncAttributeMaxDynamicSharedMemorySize, SM_TOTAL);

    int dev = 0, sms = 148;
    cudaGetDevice(&dev);
    cudaDeviceGetAttribute(&sms, cudaDevAttrMultiProcessorCount, dev);

    const int grid = (sms < n_tiles) ? sms : n_tiles;
    memunit_ws<<<grid, NTH, SM_TOTAL>>>(x, bank, out, n_tiles);
}